// round 2
// baseline (speedup 1.0000x reference)
#include <cuda_runtime.h>
#include <cuda_bf16.h>

// ---------------------------------------------------------------------------
// SurvivalGNN: 2-layer GCN (N=50000, D=128, E=800000) + 2 linear heads.
//
// Math restructuring:
//   norm(e) = dinv[src]*dinv[dst], out = segsum(h[src]*norm) + b  (incl self loop)
//   Define hs[i] = (in @ W)[i] * dinv[i]          (GEMM epilogue scale)
//   agg_pre[i]  = hs[i] + sum_{e: dst=i} hs[src]  (self-loop = init value!)
//   layer_out[i] = relu(dinv[i]*agg_pre[i] + b)   (folded into next GEMM load)
// Edge kernel is therefore a pure gather + vector red.add — no multiplies.
// ---------------------------------------------------------------------------

#define NMAX 50000
#define D 128

__device__ float g_deg [NMAX];
__device__ float g_dinv[NMAX];
__device__ float g_hs  [NMAX * D];
__device__ float g_agg [NMAX * D];

__device__ __forceinline__ void red_add_f32(float* p, float v) {
    asm volatile("red.global.add.f32 [%0], %1;" :: "l"(p), "f"(v) : "memory");
}
__device__ __forceinline__ void red_add_v4(float* p, float4 v) {
    asm volatile("red.global.add.v4.f32 [%0], {%1,%2,%3,%4};"
                 :: "l"(p), "f"(v.x), "f"(v.y), "f"(v.z), "f"(v.w) : "memory");
}

// ---- degree / dinv -------------------------------------------------------
__global__ void k_zero_deg(int n) {
    int i = blockIdx.x * blockDim.x + threadIdx.x;
    if (i < n) g_deg[i] = 0.0f;
}
__global__ void k_count_deg(const int* __restrict__ ei, int E) {
    int e = blockIdx.x * blockDim.x + threadIdx.x;
    if (e < E) red_add_f32(&g_deg[ei[E + e]], 1.0f);   // dst = ei[1][e]
}
__global__ void k_dinv(int n) {
    int i = blockIdx.x * blockDim.x + threadIdx.x;
    if (i < n) g_dinv[i] = rsqrtf(g_deg[i] + 1.0f);    // +1 self loop
}

// ---- GEMM: out_hs = out_agg = act(in) @ W * dinv[row] --------------------
// act(in) = in                       (transform == 0, layer 1: in = x)
// act(in) = relu(dinv[row]*in + b)   (transform == 1, layer 2: in = agg)
// One warp per row; W rows read as float4, L1-resident (64 KB).
__global__ void __launch_bounds__(256)
k_gemm(const float* __restrict__ in, const float* __restrict__ W,
       const float* __restrict__ bias, int transform,
       float* __restrict__ out_hs, float* __restrict__ out_agg, int n)
{
    int warp = threadIdx.x >> 5;
    int lane = threadIdx.x & 31;
    int row  = blockIdx.x * 8 + warp;
    if (row >= n) return;

    __shared__ float sx[8][D];

    float di = g_dinv[row];
    float4 v = *(const float4*)(in + (size_t)row * D + lane * 4);
    if (transform) {
        float4 b = *(const float4*)(bias + lane * 4);
        v.x = fmaxf(fmaf(di, v.x, b.x), 0.0f);
        v.y = fmaxf(fmaf(di, v.y, b.y), 0.0f);
        v.z = fmaxf(fmaf(di, v.z, b.z), 0.0f);
        v.w = fmaxf(fmaf(di, v.w, b.w), 0.0f);
    }
    *(float4*)&sx[warp][lane * 4] = v;
    __syncwarp();

    float4 acc = make_float4(0.f, 0.f, 0.f, 0.f);
    #pragma unroll 16
    for (int k = 0; k < D; k++) {
        float  xv = sx[warp][k];
        float4 w  = *(const float4*)(W + k * D + lane * 4);
        acc.x = fmaf(xv, w.x, acc.x);
        acc.y = fmaf(xv, w.y, acc.y);
        acc.z = fmaf(xv, w.z, acc.z);
        acc.w = fmaf(xv, w.w, acc.w);
    }
    acc.x *= di; acc.y *= di; acc.z *= di; acc.w *= di;

    size_t o = (size_t)row * D + lane * 4;
    *(float4*)(out_hs  + o) = acc;   // message buffer (gathered by edges)
    *(float4*)(out_agg + o) = acc;   // self-loop term = aggregation init
}

// ---- edge aggregation: agg[dst] += hs[src], one warp per edge ------------
__global__ void __launch_bounds__(256)
k_edge_agg(const int* __restrict__ ei, int E)
{
    int w    = (blockIdx.x * blockDim.x + threadIdx.x) >> 5;
    int lane = threadIdx.x & 31;
    if (w >= E) return;
    int src = ei[w];
    int dst = ei[E + w];
    float4 v = *(const float4*)(g_hs + (size_t)src * D + lane * 4);
    red_add_v4(g_agg + (size_t)dst * D + lane * 4, v);
}

// ---- heads: h = relu(dinv*agg + b2); out = [h@Wt+bt ; h@We+be] -----------
__global__ void __launch_bounds__(256)
k_heads(const float* __restrict__ b2,
        const float* __restrict__ Wt, const float* __restrict__ bt,
        const float* __restrict__ We, const float* __restrict__ be,
        float* __restrict__ out, int n)
{
    int warp = threadIdx.x >> 5;
    int lane = threadIdx.x & 31;
    int row  = blockIdx.x * 8 + warp;
    if (row >= n) return;

    float di = g_dinv[row];
    float4 a = *(const float4*)(g_agg + (size_t)row * D + lane * 4);
    float4 b = *(const float4*)(b2 + lane * 4);
    float4 h;
    h.x = fmaxf(fmaf(di, a.x, b.x), 0.0f);
    h.y = fmaxf(fmaf(di, a.y, b.y), 0.0f);
    h.z = fmaxf(fmaf(di, a.z, b.z), 0.0f);
    h.w = fmaxf(fmaf(di, a.w, b.w), 0.0f);

    float4 wt = *(const float4*)(Wt + lane * 4);
    float4 we = *(const float4*)(We + lane * 4);
    float st = h.x*wt.x + h.y*wt.y + h.z*wt.z + h.w*wt.w;
    float ev = h.x*we.x + h.y*we.y + h.z*we.z + h.w*we.w;
    #pragma unroll
    for (int off = 16; off; off >>= 1) {
        st += __shfl_xor_sync(0xFFFFFFFFu, st, off);
        ev += __shfl_xor_sync(0xFFFFFFFFu, ev, off);
    }
    if (lane == 0) {
        out[row]     = st + bt[0];
        out[n + row] = ev + be[0];
    }
}

// ---------------------------------------------------------------------------
extern "C" void kernel_launch(void* const* d_in, const int* in_sizes, int n_in,
                              void* d_out, int out_size)
{
    const float* x   = (const float*)d_in[0];
    const int*   ei  = (const int*)  d_in[1];
    const float* W1  = (const float*)d_in[2];
    const float* b1  = (const float*)d_in[3];
    const float* W2  = (const float*)d_in[4];
    const float* b2  = (const float*)d_in[5];
    const float* Wt  = (const float*)d_in[6];
    const float* bt  = (const float*)d_in[7];
    const float* We  = (const float*)d_in[8];
    const float* be  = (const float*)d_in[9];
    float* out = (float*)d_out;

    int n = in_sizes[0] / D;       // 50000
    int E = in_sizes[1] / 2;       // 800000

    float *hs, *agg;
    cudaGetSymbolAddress((void**)&hs,  g_hs);
    cudaGetSymbolAddress((void**)&agg, g_agg);

    const int T = 256;
    int nb_n = (n + T - 1) / T;
    int nb_e = (E + T - 1) / T;
    int nb_r = (n + 7) / 8;              // 8 warps (rows) per block
    int nb_w = (E * 32 + T - 1) / T;     // one warp per edge

    // degree / normalization
    k_zero_deg <<<nb_n, T>>>(n);
    k_count_deg<<<nb_e, T>>>(ei, E);
    k_dinv     <<<nb_n, T>>>(n);

    // layer 1
    k_gemm    <<<nb_r, T>>>(x, W1, nullptr, 0, hs, agg, n);
    k_edge_agg<<<nb_w, T>>>(ei, E);

    // layer 2 (input transform applies relu(dinv*agg + b1); in-place safe:
    // each block reads only its own rows before writing them)
    k_gemm    <<<nb_r, T>>>(agg, W2, b1, 1, hs, agg, n);
    k_edge_agg<<<nb_w, T>>>(ei, E);

    // heads
    k_heads<<<nb_r, T>>>(b2, Wt, bt, We, be, out, n);
}

// round 3
// speedup vs baseline: 1.9476x; 1.9476x over previous
#include <cuda_runtime.h>
#include <cuda_bf16.h>

// ---------------------------------------------------------------------------
// SurvivalGNN: 2-layer GCN (N=50000, D=128, E=800000) + 2 linear heads.
//
//   hs[i]      = (act(in) @ W)[i] * dinv[i]       (GEMM, 8 rows/warp blocked)
//   agg[i]     = hs[i] + sum_{e: dst=i} hs[src]   (CSR gather, no atomics)
//   next-in[i] = relu(dinv[i]*agg[i] + b)         (folded into next GEMM load)
// Heads fused into the second aggregation pass.
// ---------------------------------------------------------------------------

#define NMAX 50000
#define EMAX 800000
#define D 128

__device__ int   g_degi  [NMAX];
__device__ int   g_rowptr[NMAX + 1];
__device__ int   g_fill  [NMAX];
__device__ int   g_bsum  [256];
__device__ int   g_csr   [EMAX];
__device__ float g_dinv  [NMAX];
__device__ float g_hs    [NMAX * D];
__device__ float g_agg   [NMAX * D];

// ---- degree / dinv -------------------------------------------------------
__global__ void k_zero(int n) {
    int i = blockIdx.x * blockDim.x + threadIdx.x;
    if (i < n) g_degi[i] = 0;
}
__global__ void k_count_deg(const int* __restrict__ ei, int E) {
    int e = blockIdx.x * blockDim.x + threadIdx.x;
    if (e < E) atomicAdd(&g_degi[ei[E + e]], 1);       // dst = ei[1][e]
}
__global__ void k_dinv(int n) {
    int i = blockIdx.x * blockDim.x + threadIdx.x;
    if (i < n) g_dinv[i] = rsqrtf((float)g_degi[i] + 1.0f);   // +1 self loop
}

// ---- CSR build: exclusive scan of degrees, then scatter ------------------
__global__ void k_scan1(int n) {             // per-block exclusive scan
    __shared__ int s[256];
    int t = threadIdx.x, i = blockIdx.x * 256 + t;
    int v = (i < n) ? g_degi[i] : 0;
    s[t] = v; __syncthreads();
    #pragma unroll
    for (int off = 1; off < 256; off <<= 1) {
        int a = (t >= off) ? s[t - off] : 0;
        __syncthreads(); s[t] += a; __syncthreads();
    }
    if (i < n) g_rowptr[i] = s[t] - v;       // exclusive within block
    if (t == 255) g_bsum[blockIdx.x] = s[255];
}
__global__ void k_scan2(int nb) {            // scan of block sums (nb <= 256)
    __shared__ int s[256];
    int t = threadIdx.x;
    int v = (t < nb) ? g_bsum[t] : 0;
    s[t] = v; __syncthreads();
    #pragma unroll
    for (int off = 1; off < 256; off <<= 1) {
        int a = (t >= off) ? s[t - off] : 0;
        __syncthreads(); s[t] += a; __syncthreads();
    }
    if (t < nb) g_bsum[t] = s[t] - v;        // exclusive block offsets
}
__global__ void k_scan3(int n, int E) {
    int i = blockIdx.x * blockDim.x + threadIdx.x;
    if (i < n) {
        int r = g_rowptr[i] + g_bsum[i >> 8];
        g_rowptr[i] = r;
        g_fill[i]   = r;
        if (i == 0) g_rowptr[n] = E;
    }
}
__global__ void k_scatter(const int* __restrict__ ei, int E) {
    int e = blockIdx.x * blockDim.x + threadIdx.x;
    if (e < E) {
        int pos = atomicAdd(&g_fill[ei[E + e]], 1);
        g_csr[pos] = ei[e];                  // src node id
    }
}

// ---- GEMM: hs = act(in) @ W * dinv, 64 rows/block, 8 rows/warp -----------
// act = identity (transform=0) or relu(dinv*in + bias) (transform=1)
__global__ void __launch_bounds__(256)
k_gemm(const float* __restrict__ in, const float* __restrict__ W,
       const float* __restrict__ bias, int transform,
       float* __restrict__ out_hs, int n)
{
    __shared__ float sx[64][D];
    int t = threadIdx.x;
    int base = blockIdx.x * 64;

    // cooperative load of 64 input rows (2048 float4s)
    #pragma unroll
    for (int j = 0; j < 8; j++) {
        int f = j * 256 + t;
        int r = f >> 5, c = f & 31;
        int row = base + r;
        if (row < n) {
            float4 v = *(const float4*)(in + (size_t)row * D + c * 4);
            if (transform) {
                float  di = g_dinv[row];
                float4 b  = *(const float4*)(bias + c * 4);
                v.x = fmaxf(fmaf(di, v.x, b.x), 0.0f);
                v.y = fmaxf(fmaf(di, v.y, b.y), 0.0f);
                v.z = fmaxf(fmaf(di, v.z, b.z), 0.0f);
                v.w = fmaxf(fmaf(di, v.w, b.w), 0.0f);
            }
            *(float4*)&sx[r][c * 4] = v;
        }
    }
    __syncthreads();

    int warp = t >> 5, lane = t & 31;
    int r0 = warp * 8;
    float4 acc[8];
    #pragma unroll
    for (int r = 0; r < 8; r++) acc[r] = make_float4(0.f, 0.f, 0.f, 0.f);

    const float* Wp = W + lane * 4;
    #pragma unroll 4
    for (int k = 0; k < D; k++) {
        float4 w = *(const float4*)(Wp + k * D);
        #pragma unroll
        for (int r = 0; r < 8; r++) {
            float xv = sx[r0 + r][k];
            acc[r].x = fmaf(xv, w.x, acc[r].x);
            acc[r].y = fmaf(xv, w.y, acc[r].y);
            acc[r].z = fmaf(xv, w.z, acc[r].z);
            acc[r].w = fmaf(xv, w.w, acc[r].w);
        }
    }

    #pragma unroll
    for (int r = 0; r < 8; r++) {
        int row = base + r0 + r;
        if (row < n) {
            float di = g_dinv[row];
            float4 a = acc[r];
            a.x *= di; a.y *= di; a.z *= di; a.w *= di;
            *(float4*)(out_hs + (size_t)row * D + lane * 4) = a;
        }
    }
}

// ---- aggregation (layer 1): agg[i] = hs[i] + sum_nbr hs[src] -------------
__global__ void __launch_bounds__(256)
k_agg(int n)
{
    int w    = (blockIdx.x * blockDim.x + threadIdx.x) >> 5;
    int lane = threadIdx.x & 31;
    if (w >= n) return;

    size_t o = (size_t)w * D + lane * 4;
    float4 acc = *(const float4*)(g_hs + o);       // self loop
    int e   = g_rowptr[w];
    int end = g_rowptr[w + 1];
    for (; e + 1 < end; e += 2) {
        int s0 = g_csr[e], s1 = g_csr[e + 1];
        float4 v0 = *(const float4*)(g_hs + (size_t)s0 * D + lane * 4);
        float4 v1 = *(const float4*)(g_hs + (size_t)s1 * D + lane * 4);
        acc.x += v0.x + v1.x; acc.y += v0.y + v1.y;
        acc.z += v0.z + v1.z; acc.w += v0.w + v1.w;
    }
    if (e < end) {
        int s0 = g_csr[e];
        float4 v0 = *(const float4*)(g_hs + (size_t)s0 * D + lane * 4);
        acc.x += v0.x; acc.y += v0.y; acc.z += v0.z; acc.w += v0.w;
    }
    *(float4*)(g_agg + o) = acc;
}

// ---- aggregation (layer 2) fused with heads ------------------------------
__global__ void __launch_bounds__(256)
k_agg_heads(const float* __restrict__ b2,
            const float* __restrict__ Wt, const float* __restrict__ bt,
            const float* __restrict__ We, const float* __restrict__ be,
            float* __restrict__ out, int n)
{
    int w    = (blockIdx.x * blockDim.x + threadIdx.x) >> 5;
    int lane = threadIdx.x & 31;
    if (w >= n) return;

    size_t o = (size_t)w * D + lane * 4;
    float4 acc = *(const float4*)(g_hs + o);       // self loop
    int e   = g_rowptr[w];
    int end = g_rowptr[w + 1];
    for (; e + 1 < end; e += 2) {
        int s0 = g_csr[e], s1 = g_csr[e + 1];
        float4 v0 = *(const float4*)(g_hs + (size_t)s0 * D + lane * 4);
        float4 v1 = *(const float4*)(g_hs + (size_t)s1 * D + lane * 4);
        acc.x += v0.x + v1.x; acc.y += v0.y + v1.y;
        acc.z += v0.z + v1.z; acc.w += v0.w + v1.w;
    }
    if (e < end) {
        int s0 = g_csr[e];
        float4 v0 = *(const float4*)(g_hs + (size_t)s0 * D + lane * 4);
        acc.x += v0.x; acc.y += v0.y; acc.z += v0.z; acc.w += v0.w;
    }

    // h = relu(dinv*acc + b2); out = [h@Wt+bt ; h@We+be]
    float  di = g_dinv[w];
    float4 b  = *(const float4*)(b2 + lane * 4);
    float4 h;
    h.x = fmaxf(fmaf(di, acc.x, b.x), 0.0f);
    h.y = fmaxf(fmaf(di, acc.y, b.y), 0.0f);
    h.z = fmaxf(fmaf(di, acc.z, b.z), 0.0f);
    h.w = fmaxf(fmaf(di, acc.w, b.w), 0.0f);

    float4 wt = *(const float4*)(Wt + lane * 4);
    float4 we = *(const float4*)(We + lane * 4);
    float st = h.x*wt.x + h.y*wt.y + h.z*wt.z + h.w*wt.w;
    float ev = h.x*we.x + h.y*we.y + h.z*we.z + h.w*we.w;
    #pragma unroll
    for (int off = 16; off; off >>= 1) {
        st += __shfl_xor_sync(0xFFFFFFFFu, st, off);
        ev += __shfl_xor_sync(0xFFFFFFFFu, ev, off);
    }
    if (lane == 0) {
        out[w]     = st + bt[0];
        out[n + w] = ev + be[0];
    }
}

// ---------------------------------------------------------------------------
extern "C" void kernel_launch(void* const* d_in, const int* in_sizes, int n_in,
                              void* d_out, int out_size)
{
    const float* x   = (const float*)d_in[0];
    const int*   ei  = (const int*)  d_in[1];
    const float* W1  = (const float*)d_in[2];
    const float* b1  = (const float*)d_in[3];
    const float* W2  = (const float*)d_in[4];
    const float* b2  = (const float*)d_in[5];
    const float* Wt  = (const float*)d_in[6];
    const float* bt  = (const float*)d_in[7];
    const float* We  = (const float*)d_in[8];
    const float* be  = (const float*)d_in[9];
    float* out = (float*)d_out;

    int n = in_sizes[0] / D;       // 50000
    int E = in_sizes[1] / 2;       // 800000

    float *hs, *agg;
    cudaGetSymbolAddress((void**)&hs,  g_hs);
    cudaGetSymbolAddress((void**)&agg, g_agg);

    const int T = 256;
    int nb_n  = (n + T - 1) / T;         // node-parallel 1D
    int nb_e  = (E + T - 1) / T;         // edge-parallel 1D
    int nb_g  = (n + 63) / 64;           // GEMM: 64 rows per block
    int nb_w  = (n + 7) / 8;             // warp-per-node kernels

    // normalization + CSR
    k_zero     <<<nb_n, T>>>(n);
    k_count_deg<<<nb_e, T>>>(ei, E);
    k_dinv     <<<nb_n, T>>>(n);
    k_scan1    <<<nb_n, T>>>(n);
    k_scan2    <<<1,    T>>>(nb_n);
    k_scan3    <<<nb_n, T>>>(n, E);
    k_scatter  <<<nb_e, T>>>(ei, E);

    // layer 1
    k_gemm<<<nb_g, T>>>(x, W1, nullptr, 0, hs, n);
    k_agg <<<nb_w, T>>>(n);

    // layer 2 + heads
    k_gemm     <<<nb_g, T>>>(agg, W2, b1, 1, hs, n);
    k_agg_heads<<<nb_w, T>>>(b2, Wt, bt, We, be, out, n);
}